// round 4
// baseline (speedup 1.0000x reference)
#include <cuda_runtime.h>
#include <cuda_bf16.h>
#include <cstdint>

// ---------------------------------------------------------------------------
// Problem constants (fixed shapes: B=4, N=2048, D=1024, BULK=10)
// ---------------------------------------------------------------------------
#define M_DIM 8192          // B*N rows
#define D_DIM 1024          // model dim (= K = N of the collapsed GEMM)
#define BULK  10
#define W_COLS (D_DIM * BULK)   // 10240

// Scan-collapse weights: w_j = (H_10 - H_j)/10
__device__ const float c_ws[10] = {
    0.29289682539682538f, 0.19289682539682540f, 0.14289682539682540f,
    0.10956349206349206f, 0.08456349206349207f, 0.06456349206349207f,
    0.04789682539682541f, 0.03361111111111112f, 0.02111111111111111f,
    0.01000000000000000f
};

// ---------------------------------------------------------------------------
// Scratch (no allocations allowed -> __device__ globals)
// ---------------------------------------------------------------------------
__device__ __nv_bfloat16 g_Xh[(size_t)M_DIM * D_DIM];   // X hi  (row-major M x K)
__device__ __nv_bfloat16 g_Xl[(size_t)M_DIM * D_DIM];   // X lo
__device__ __nv_bfloat16 g_Wh[(size_t)D_DIM * D_DIM];   // W_eff^T hi  ([n][k], k contiguous)
__device__ __nv_bfloat16 g_Wl[(size_t)D_DIM * D_DIM];   // W_eff^T lo
__device__ float         g_beff[D_DIM];

// ---------------------------------------------------------------------------
// Helpers
// ---------------------------------------------------------------------------
__device__ __forceinline__ void split_bf16(float v, __nv_bfloat16& h, __nv_bfloat16& l) {
    h = __float2bfloat16_rn(v);
    l = __float2bfloat16_rn(v - __bfloat162float(h));
}

__device__ __forceinline__ void cp16(__nv_bfloat16* s, const __nv_bfloat16* g) {
    uint32_t sa = (uint32_t)__cvta_generic_to_shared(s);
    asm volatile("cp.async.cg.shared.global [%0], [%1], 16;\n" :: "r"(sa), "l"(g));
}
__device__ __forceinline__ void cp_commit() {
    asm volatile("cp.async.commit_group;\n");
}
template <int Ng>
__device__ __forceinline__ void cp_wait() {
    asm volatile("cp.async.wait_group %0;\n" :: "n"(Ng));
}

__device__ __forceinline__ uint32_t lds32(const __nv_bfloat16* p) {
    return *reinterpret_cast<const uint32_t*>(p);
}

__device__ __forceinline__ void mma16816(float* c, const uint32_t* a, const uint32_t* b) {
    asm volatile(
        "mma.sync.aligned.m16n8k16.row.col.f32.bf16.bf16.f32 "
        "{%0,%1,%2,%3}, {%4,%5,%6,%7}, {%8,%9}, {%0,%1,%2,%3};\n"
        : "+f"(c[0]), "+f"(c[1]), "+f"(c[2]), "+f"(c[3])
        : "r"(a[0]), "r"(a[1]), "r"(a[2]), "r"(a[3]), "r"(b[0]), "r"(b[1]));
}

// ---------------------------------------------------------------------------
// P1: X (fp32) -> bf16 hi/lo pair.  One float4 per thread.
// ---------------------------------------------------------------------------
struct __align__(8) bf16x4 { __nv_bfloat16 a, b, c, d; };

__global__ void prep_x_kernel(const float* __restrict__ X) {
    int i = blockIdx.x * blockDim.x + threadIdx.x;   // float4 index
    const int total4 = (M_DIM * D_DIM) / 4;
    if (i >= total4) return;
    float4 v = reinterpret_cast<const float4*>(X)[i];
    bf16x4 h, l;
    split_bf16(v.x, h.a, l.a);
    split_bf16(v.y, h.b, l.b);
    split_bf16(v.z, h.c, l.c);
    split_bf16(v.w, h.d, l.d);
    reinterpret_cast<bf16x4*>(g_Xh)[i] = h;
    reinterpret_cast<bf16x4*>(g_Xl)[i] = l;
}

// ---------------------------------------------------------------------------
// P2: W_eff[i][j] = sum_s w_s * W[i][s*1024 + j], written TRANSPOSED
//     (g_W*[j*1024 + i]) and split into bf16 hi/lo.  32x32 smem transpose.
//     grid (32, 32), block (32, 8).
// ---------------------------------------------------------------------------
__global__ void prep_w_kernel(const float* __restrict__ W) {
    __shared__ float s[32][33];
    const int bx = blockIdx.x;           // j (output col / transposed row) tile
    const int by = blockIdx.y;           // i (input row / k) tile
    const int tx = threadIdx.x;          // 0..31
    const int ty = threadIdx.y;          // 0..7
    const int j = bx * 32 + tx;

    #pragma unroll
    for (int r = 0; r < 4; r++) {
        const int il = ty + 8 * r;
        const int i = by * 32 + il;
        const float* row = W + (size_t)i * W_COLS + j;
        float acc = 0.f;
        #pragma unroll
        for (int sidx = 0; sidx < BULK; sidx++)
            acc += c_ws[sidx] * row[sidx * D_DIM];
        s[il][tx] = acc;
    }
    __syncthreads();

    #pragma unroll
    for (int r = 0; r < 4; r++) {
        const int jl = ty + 8 * r;       // transposed row within tile
        const float v = s[tx][jl];       // (i_local = tx, j_local = jl)
        __nv_bfloat16 h, l;
        split_bf16(v, h, l);
        const size_t o = (size_t)(bx * 32 + jl) * D_DIM + by * 32 + tx;
        g_Wh[o] = h;
        g_Wl[o] = l;
    }
}

// ---------------------------------------------------------------------------
// P0: b_eff[j] = sum_s w_s * b[s*1024 + j]
// ---------------------------------------------------------------------------
__global__ void prep_b_kernel(const float* __restrict__ b) {
    int j = blockIdx.x * blockDim.x + threadIdx.x;
    if (j >= D_DIM) return;
    float acc = 0.f;
    #pragma unroll
    for (int sidx = 0; sidx < BULK; sidx++)
        acc += c_ws[sidx] * b[sidx * D_DIM + j];
    g_beff[j] = acc;
}

// ---------------------------------------------------------------------------
// GEMM:  out[8192,1024] = Xh@Wh + Xh@Wl + Xl@Wh  (+ b_eff), fp32 accum.
//   CTA tile 128x128, K-chunk 32, 8 warps (2x4), warp tile 64x32.
//   Double-buffered cp.async. Padded smem rows (40 bf16) for conflict-free LDS.
// ---------------------------------------------------------------------------
#define BM 128
#define BN 128
#define BK 32
#define LDT 40                       // padded row length in bf16 elements
#define TILE_ELEMS (128 * LDT)       // 5120
#define STAGE_ELEMS (4 * TILE_ELEMS) // Ah, Al, Bh, Bl
#define SMEM_BYTES (2 * STAGE_ELEMS * 2)  // 81920 B
#define K_TILES (D_DIM / BK)         // 32

__device__ __forceinline__ void load_stage(__nv_bfloat16* smem, int st,
                                           int m0, int n0, int kc, int tid) {
    __nv_bfloat16* base = smem + st * STAGE_ELEMS;
    __nv_bfloat16* sAh = base;
    __nv_bfloat16* sAl = base + TILE_ELEMS;
    __nv_bfloat16* sBh = base + 2 * TILE_ELEMS;
    __nv_bfloat16* sBl = base + 3 * TILE_ELEMS;
    #pragma unroll
    for (int cc = 0; cc < 2; cc++) {
        const int c = tid + cc * 256;      // 0..511
        const int r = c >> 2;              // row 0..127
        const int seg = c & 3;             // 16B segment within 64B row
        const int koff = kc * BK + seg * 8;
        const int soff = r * LDT + seg * 8;
        cp16(sAh + soff, g_Xh + (size_t)(m0 + r) * D_DIM + koff);
        cp16(sAl + soff, g_Xl + (size_t)(m0 + r) * D_DIM + koff);
        cp16(sBh + soff, g_Wh + (size_t)(n0 + r) * D_DIM + koff);
        cp16(sBl + soff, g_Wl + (size_t)(n0 + r) * D_DIM + koff);
    }
}

__global__ __launch_bounds__(256)
void gemm_bf16x3_kernel(float* __restrict__ out) {
    extern __shared__ __nv_bfloat16 smem[];
    const int tid = threadIdx.x;
    const int m0 = blockIdx.y * BM;
    const int n0 = blockIdx.x * BN;

    const int warp = tid >> 5, lane = tid & 31;
    const int wm = warp >> 2;            // 0..1  (64-row group)
    const int wn = warp & 3;             // 0..3  (32-col group)
    const int grp = lane >> 2;           // 0..7
    const int tig = lane & 3;            // 0..3

    float acc[4][4][4];
    #pragma unroll
    for (int ma = 0; ma < 4; ma++)
        #pragma unroll
        for (int na = 0; na < 4; na++)
            #pragma unroll
            for (int q = 0; q < 4; q++) acc[ma][na][q] = 0.f;

    load_stage(smem, 0, m0, n0, 0, tid);
    cp_commit();

    #pragma unroll 1
    for (int kc = 0; kc < K_TILES; kc++) {
        if (kc + 1 < K_TILES) {
            load_stage(smem, (kc + 1) & 1, m0, n0, kc + 1, tid);
            cp_commit();
            cp_wait<1>();
        } else {
            cp_wait<0>();
        }
        __syncthreads();

        const __nv_bfloat16* base = smem + (kc & 1) * STAGE_ELEMS;
        const __nv_bfloat16* sAh = base;
        const __nv_bfloat16* sAl = base + TILE_ELEMS;
        const __nv_bfloat16* sBh = base + 2 * TILE_ELEMS;
        const __nv_bfloat16* sBl = base + 3 * TILE_ELEMS;

        #pragma unroll
        for (int ks = 0; ks < 2; ks++) {
            const int kb = ks * 16 + tig * 2;
            uint32_t bh[4][2], bl[4][2];
            #pragma unroll
            for (int na = 0; na < 4; na++) {
                const int n = wn * 32 + na * 8 + grp;
                bh[na][0] = lds32(sBh + n * LDT + kb);
                bh[na][1] = lds32(sBh + n * LDT + kb + 8);
                bl[na][0] = lds32(sBl + n * LDT + kb);
                bl[na][1] = lds32(sBl + n * LDT + kb + 8);
            }
            #pragma unroll
            for (int ma = 0; ma < 4; ma++) {
                const int m = wm * 64 + ma * 16 + grp;
                uint32_t ah[4], al[4];
                ah[0] = lds32(sAh + m * LDT + kb);
                ah[1] = lds32(sAh + (m + 8) * LDT + kb);
                ah[2] = lds32(sAh + m * LDT + kb + 8);
                ah[3] = lds32(sAh + (m + 8) * LDT + kb + 8);
                al[0] = lds32(sAl + m * LDT + kb);
                al[1] = lds32(sAl + (m + 8) * LDT + kb);
                al[2] = lds32(sAl + m * LDT + kb + 8);
                al[3] = lds32(sAl + (m + 8) * LDT + kb + 8);
                #pragma unroll
                for (int na = 0; na < 4; na++) {
                    mma16816(acc[ma][na], ah, bh[na]);   // hi*hi
                    mma16816(acc[ma][na], ah, bl[na]);   // hi*lo
                    mma16816(acc[ma][na], al, bh[na]);   // lo*hi
                }
            }
        }
        __syncthreads();
    }

    // Epilogue: add bias, store fp32 (float2 per fragment row)
    #pragma unroll
    for (int ma = 0; ma < 4; ma++) {
        const int row = m0 + wm * 64 + ma * 16 + grp;
        #pragma unroll
        for (int na = 0; na < 4; na++) {
            const int col = n0 + wn * 32 + na * 8 + tig * 2;
            const float b0 = g_beff[col];
            const float b1 = g_beff[col + 1];
            float2 v0 = make_float2(acc[ma][na][0] + b0, acc[ma][na][1] + b1);
            float2 v1 = make_float2(acc[ma][na][2] + b0, acc[ma][na][3] + b1);
            *reinterpret_cast<float2*>(out + (size_t)row * D_DIM + col) = v0;
            *reinterpret_cast<float2*>(out + (size_t)(row + 8) * D_DIM + col) = v1;
        }
    }
}

// ---------------------------------------------------------------------------
// Launch
// ---------------------------------------------------------------------------
extern "C" void kernel_launch(void* const* d_in, const int* in_sizes, int n_in,
                              void* d_out, int out_size) {
    const float* X = nullptr;
    const float* W = nullptr;
    const float* b = nullptr;
    for (int i = 0; i < n_in; i++) {
        if (in_sizes[i] == M_DIM * D_DIM)       X = (const float*)d_in[i];
        else if (in_sizes[i] == D_DIM * W_COLS) W = (const float*)d_in[i];
        else if (in_sizes[i] == W_COLS)         b = (const float*)d_in[i];
    }
    float* out = (float*)d_out;

    // P1: X -> bf16 hi/lo    (8192*1024/4 float4s)
    prep_x_kernel<<<(M_DIM * D_DIM / 4 + 255) / 256, 256>>>(X);
    // P2: W_eff^T hi/lo
    prep_w_kernel<<<dim3(D_DIM / 32, D_DIM / 32), dim3(32, 8)>>>(W);
    // P0: bias
    prep_b_kernel<<<(D_DIM + 255) / 256, 256>>>(b);

    // GEMM
    cudaFuncSetAttribute(gemm_bf16x3_kernel,
                         cudaFuncAttributeMaxDynamicSharedMemorySize, SMEM_BYTES);
    gemm_bf16x3_kernel<<<dim3(D_DIM / BN, M_DIM / BM), 256, SMEM_BYTES>>>(out);
}

// round 7
// speedup vs baseline: 1.3142x; 1.3142x over previous
#include <cuda_runtime.h>
#include <cuda_fp16.h>
#include <cstdint>

// ---------------------------------------------------------------------------
// Problem constants (fixed shapes: B=4, N=2048, D=1024, BULK=10)
//
// Algebra: the scan g_k = g_{k-1} + (c_k - g_{k-1})/(k+1) is a running mean,
// so mean_k g_k = sum_j w_j c_j with w_j = (H_10 - H_j)/10, and the whole op
// collapses to out = X @ W_eff + b_eff with W_eff = sum_j w_j W[:, jD:(j+1)D].
//
// Precision: fp16 2-term split. out = Xh@(Wh + Wl); dropped Xl@W term is
// ~2^-11.6 relative (~3e-4 aggregate) < 1e-3 gate.
// ---------------------------------------------------------------------------
#define M_DIM 8192
#define D_DIM 1024
#define BULK  10
#define W_COLS (D_DIM * BULK)

__device__ const float c_ws[10] = {
    0.29289682539682538f, 0.19289682539682540f, 0.14289682539682540f,
    0.10956349206349206f, 0.08456349206349207f, 0.06456349206349207f,
    0.04789682539682541f, 0.03361111111111112f, 0.02111111111111111f,
    0.01000000000000000f
};

// ---------------------------------------------------------------------------
// Scratch (__device__ globals; no allocations allowed)
// ---------------------------------------------------------------------------
__device__ __half g_Xh[(size_t)M_DIM * D_DIM];   // X hi (fp16, row-major M x K)
__device__ __half g_Wh[(size_t)D_DIM * D_DIM];   // W_eff^T hi ([n][k], k contig)
__device__ __half g_Wl[(size_t)D_DIM * D_DIM];   // W_eff^T lo
__device__ float  g_beff[D_DIM];

// ---------------------------------------------------------------------------
// Helpers
// ---------------------------------------------------------------------------
__device__ __forceinline__ uint32_t smem_u32(const void* p) {
    uint32_t a;
    asm("{ .reg .u64 t; cvta.to.shared.u64 t, %1; cvt.u32.u64 %0, t; }" : "=r"(a) : "l"(p));
    return a;
}
__device__ __forceinline__ void cp16(uint32_t saddr, const void* g) {
    asm volatile("cp.async.cg.shared.global [%0], [%1], 16;\n" :: "r"(saddr), "l"(g));
}
__device__ __forceinline__ void cp_commit() {
    asm volatile("cp.async.commit_group;\n");
}
template <int Ng>
__device__ __forceinline__ void cp_wait() {
    asm volatile("cp.async.wait_group %0;\n" :: "n"(Ng));
}

#define LDMX4(r0, r1, r2, r3, addr)                                            \
    asm volatile("ldmatrix.sync.aligned.m8n8.x4.shared.b16 {%0,%1,%2,%3}, [%4];" \
                 : "=r"(r0), "=r"(r1), "=r"(r2), "=r"(r3) : "r"(addr))

__device__ __forceinline__ void mma16816(float* c, const uint32_t* a, const uint32_t* b) {
    asm volatile(
        "mma.sync.aligned.m16n8k16.row.col.f32.f16.f16.f32 "
        "{%0,%1,%2,%3}, {%4,%5,%6,%7}, {%8,%9}, {%0,%1,%2,%3};\n"
        : "+f"(c[0]), "+f"(c[1]), "+f"(c[2]), "+f"(c[3])
        : "r"(a[0]), "r"(a[1]), "r"(a[2]), "r"(a[3]), "r"(b[0]), "r"(b[1]));
}

// ---------------------------------------------------------------------------
// P1: X (fp32) -> fp16 hi only.  One float4 -> half4 per thread.
// ---------------------------------------------------------------------------
struct __align__(8) h4 { __half a, b, c, d; };

__global__ void prep_x_kernel(const float* __restrict__ X) {
    int i = blockIdx.x * blockDim.x + threadIdx.x;
    const int total4 = (M_DIM * D_DIM) / 4;
    if (i >= total4) return;
    float4 v = reinterpret_cast<const float4*>(X)[i];
    h4 h;
    h.a = __float2half_rn(v.x);
    h.b = __float2half_rn(v.y);
    h.c = __float2half_rn(v.z);
    h.d = __float2half_rn(v.w);
    reinterpret_cast<h4*>(g_Xh)[i] = h;
}

// ---------------------------------------------------------------------------
// P2: W_eff[i][j] = sum_s w_s * W[i][s*1024 + j], transposed + fp16 hi/lo split
// ---------------------------------------------------------------------------
__global__ void prep_w_kernel(const float* __restrict__ W) {
    __shared__ float s[32][33];
    const int bx = blockIdx.x, by = blockIdx.y;
    const int tx = threadIdx.x, ty = threadIdx.y;
    const int j = bx * 32 + tx;

    #pragma unroll
    for (int r = 0; r < 4; r++) {
        const int il = ty + 8 * r;
        const int i = by * 32 + il;
        const float* row = W + (size_t)i * W_COLS + j;
        float acc = 0.f;
        #pragma unroll
        for (int sidx = 0; sidx < BULK; sidx++)
            acc += c_ws[sidx] * row[sidx * D_DIM];
        s[il][tx] = acc;
    }
    __syncthreads();

    #pragma unroll
    for (int r = 0; r < 4; r++) {
        const int jl = ty + 8 * r;
        const float v = s[tx][jl];
        __half h = __float2half_rn(v);
        __half l = __float2half_rn(v - __half2float(h));
        const size_t o = (size_t)(bx * 32 + jl) * D_DIM + by * 32 + tx;
        g_Wh[o] = h;
        g_Wl[o] = l;
    }
}

__global__ void prep_b_kernel(const float* __restrict__ b) {
    int j = blockIdx.x * blockDim.x + threadIdx.x;
    if (j >= D_DIM) return;
    float acc = 0.f;
    #pragma unroll
    for (int sidx = 0; sidx < BULK; sidx++)
        acc += c_ws[sidx] * b[sidx * D_DIM + j];
    g_beff[j] = acc;
}

// ---------------------------------------------------------------------------
// GEMM: out[8192,1024] = Xh@Wh^T + Xh@Wl^T + b_eff, fp32 accum.
//   CTA 128x128, BK=32, 8 warps (2x4) x warp tile 64x32.
//   3-stage cp.async pipeline, ldmatrix.x4 fragment loads, 1 sync/chunk.
//   Rows padded to 40 halves (80 B): ldmatrix row banks (20*r mod 32) cover
//   all 32 banks exactly once across 16 rows -> conflict-free.
// ---------------------------------------------------------------------------
#define BM 128
#define BN 128
#define BK 32
#define LDT 40                          // padded row length (halves)
#define ROWB (LDT * 2)                  // 80 bytes
#define TILE_B (128 * ROWB)             // 10240 B per tile
#define OFF_A 0
#define OFF_BH TILE_B
#define OFF_BL (2 * TILE_B)
#define STAGE_B (3 * TILE_B)            // 30720 B
#define NSTAGE 3
#define SMEM_BYTES (NSTAGE * STAGE_B)   // 92160 B
#define K_TILES (D_DIM / BK)            // 32

__device__ __forceinline__ void load_stage(uint32_t sb, int s, int c,
                                           int m0, int n0, int tid) {
    const uint32_t stg = sb + s * STAGE_B;
    const int k0 = c * BK;
    #pragma unroll
    for (int it = 0; it < 2; it++) {
        const int o = tid + it * 256;          // 0..511
        const int r = o >> 2;                  // row 0..127
        const int seg = o & 3;                 // 16B segment
        const uint32_t so = (uint32_t)(r * ROWB + seg * 16);
        const int ke = k0 + seg * 8;
        cp16(stg + OFF_A + so, g_Xh + (size_t)(m0 + r) * D_DIM + ke);
        cp16(stg + OFF_BH + so, g_Wh + (size_t)(n0 + r) * D_DIM + ke);
        cp16(stg + OFF_BL + so, g_Wl + (size_t)(n0 + r) * D_DIM + ke);
    }
}

__global__ __launch_bounds__(256, 2)
void gemm_f16x2_kernel(float* __restrict__ out) {
    extern __shared__ __align__(128) char smem[];
    const uint32_t sb = smem_u32(smem);
    const int tid = threadIdx.x;
    const int m0 = blockIdx.y * BM;
    const int n0 = blockIdx.x * BN;

    const int warp = tid >> 5, lane = tid & 31;
    const int wm = warp >> 2;               // 0..1
    const int wn = warp & 3;                // 0..3
    const int grp = lane >> 2;              // 0..7
    const int tig = lane & 3;               // 0..3

    // ldmatrix per-lane byte offset: row = lane&15, k-seg = (lane>>4)*8 halves
    const uint32_t lmo = (uint32_t)(((lane & 15) * LDT + ((lane >> 4) << 3)) * 2);

    float acc[4][4][4];
    #pragma unroll
    for (int ma = 0; ma < 4; ma++)
        #pragma unroll
        for (int na = 0; na < 4; na++)
            #pragma unroll
            for (int q = 0; q < 4; q++) acc[ma][na][q] = 0.f;

    load_stage(sb, 0, 0, m0, n0, tid);
    cp_commit();
    load_stage(sb, 1, 1, m0, n0, tid);
    cp_commit();

    int s = 0;
    #pragma unroll 1
    for (int c = 0; c < K_TILES; c++) {
        if (c < K_TILES - 1) { cp_wait<1>(); } else { cp_wait<0>(); }
        __syncthreads();

        const uint32_t stg = sb + s * STAGE_B;
        const uint32_t aA  = stg + OFF_A  + lmo + (uint32_t)((wm * 64) * ROWB);
        const uint32_t aBh = stg + OFF_BH + lmo + (uint32_t)((wn * 32) * ROWB);
        const uint32_t aBl = stg + OFF_BL + lmo + (uint32_t)((wn * 32) * ROWB);

        #pragma unroll
        for (int ks = 0; ks < 2; ks++) {
            const uint32_t ko = (uint32_t)(ks * 32);   // 16 halves = 32 B
            uint32_t bh[4][2], bl[4][2];
            #pragma unroll
            for (int p = 0; p < 2; p++) {
                uint32_t t0, t1, t2, t3;
                LDMX4(t0, t1, t2, t3, aBh + (uint32_t)(p * 16 * ROWB) + ko);
                bh[2 * p][0] = t0; bh[2 * p + 1][0] = t1;
                bh[2 * p][1] = t2; bh[2 * p + 1][1] = t3;
                LDMX4(t0, t1, t2, t3, aBl + (uint32_t)(p * 16 * ROWB) + ko);
                bl[2 * p][0] = t0; bl[2 * p + 1][0] = t1;
                bl[2 * p][1] = t2; bl[2 * p + 1][1] = t3;
            }
            #pragma unroll
            for (int ma = 0; ma < 4; ma++) {
                uint32_t a[4];
                LDMX4(a[0], a[1], a[2], a[3], aA + (uint32_t)(ma * 16 * ROWB) + ko);
                #pragma unroll
                for (int na = 0; na < 4; na++) {
                    mma16816(acc[ma][na], a, bh[na]);
                    mma16816(acc[ma][na], a, bl[na]);
                }
            }
        }

        if (c + 2 < K_TILES) {
            load_stage(sb, (s + 2 >= NSTAGE) ? s + 2 - NSTAGE : s + 2, c + 2,
                       m0, n0, tid);
            cp_commit();
        }
        s = (s + 1 == NSTAGE) ? 0 : s + 1;
    }

    // Epilogue: bias + fp32 stores (fragment: c0,c1 @ row, c2,c3 @ row+8)
    #pragma unroll
    for (int ma = 0; ma < 4; ma++) {
        const int row = m0 + wm * 64 + ma * 16 + grp;
        #pragma unroll
        for (int na = 0; na < 4; na++) {
            const int col = n0 + wn * 32 + na * 8 + tig * 2;
            const float b0 = g_beff[col];
            const float b1 = g_beff[col + 1];
            float2 v0 = make_float2(acc[ma][na][0] + b0, acc[ma][na][1] + b1);
            float2 v1 = make_float2(acc[ma][na][2] + b0, acc[ma][na][3] + b1);
            *reinterpret_cast<float2*>(out + (size_t)row * D_DIM + col) = v0;
            *reinterpret_cast<float2*>(out + (size_t)(row + 8) * D_DIM + col) = v1;
        }
    }
}

// ---------------------------------------------------------------------------
// Launch
// ---------------------------------------------------------------------------
extern "C" void kernel_launch(void* const* d_in, const int* in_sizes, int n_in,
                              void* d_out, int out_size) {
    const float* X = nullptr;
    const float* W = nullptr;
    const float* b = nullptr;
    for (int i = 0; i < n_in; i++) {
        if (in_sizes[i] == M_DIM * D_DIM)       X = (const float*)d_in[i];
        else if (in_sizes[i] == D_DIM * W_COLS) W = (const float*)d_in[i];
        else if (in_sizes[i] == W_COLS)         b = (const float*)d_in[i];
    }
    float* out = (float*)d_out;

    static bool attr_set = false;
    if (!attr_set) {
        cudaFuncSetAttribute(gemm_f16x2_kernel,
                             cudaFuncAttributeMaxDynamicSharedMemorySize, SMEM_BYTES);
        attr_set = true;
    }

    prep_x_kernel<<<(M_DIM * D_DIM / 4 + 255) / 256, 256>>>(X);
    prep_w_kernel<<<dim3(D_DIM / 32, D_DIM / 32), dim3(32, 8)>>>(W);
    prep_b_kernel<<<(D_DIM + 255) / 256, 256>>>(b);

    gemm_f16x2_kernel<<<dim3(D_DIM / BN, M_DIM / BM), 256, SMEM_BYTES>>>(out);
}